// round 1
// baseline (speedup 1.0000x reference)
#include <cuda_runtime.h>
#include <cstdint>

#define BB 16
#define NN 16
#define HH 512
#define WW 512
#define HW (HH*WW)          // 262144
#define Q4 (HW/4)           // 65536 float4 per (b,n) plane
#define CHUNKS 16           // grid.x for overlap kernel
#define PER_CHUNK (Q4/CHUNKS)  // 4096 float4 per block
#define THREADS 256

__device__ float g_overlap[BB*NN];
__device__ float g_tarea[BB];

__global__ void zero_kernel() {
    int i = threadIdx.x;
    if (i < BB*NN) g_overlap[i] = 0.0f;
    if (i < BB)    g_tarea[i]   = 0.0f;
}

// grid: (CHUNKS, B*N), block: THREADS
// overlap[bn] += sum(masks[bn] * target[b]) over this chunk.
// The n==0 slice of each batch also accumulates target_area[b]
// (target data is already in registers there; ~free).
__global__ __launch_bounds__(THREADS)
void overlap_kernel(const float4* __restrict__ masks,
                    const float4* __restrict__ target) {
    const int bn = blockIdx.y;
    const int b  = bn >> 4;           // / NN
    const int n  = bn & 15;
    const float4* m = masks  + (size_t)bn * Q4 + (size_t)blockIdx.x * PER_CHUNK;
    const float4* t = target + (size_t)b  * Q4 + (size_t)blockIdx.x * PER_CHUNK;

    float acc = 0.0f;
    float tac = 0.0f;
    #pragma unroll 4
    for (int i = threadIdx.x; i < PER_CHUNK; i += THREADS) {
        float4 a = m[i];
        float4 c = t[i];
        acc += a.x*c.x + a.y*c.y + a.z*c.z + a.w*c.w;
        if (n == 0) tac += c.x + c.y + c.z + c.w;
    }

    // block reduction
    __shared__ float s_acc[THREADS/32];
    __shared__ float s_tac[THREADS/32];
    const int lane = threadIdx.x & 31;
    const int wid  = threadIdx.x >> 5;
    #pragma unroll
    for (int off = 16; off > 0; off >>= 1) {
        acc += __shfl_xor_sync(0xffffffff, acc, off);
        tac += __shfl_xor_sync(0xffffffff, tac, off);
    }
    if (lane == 0) { s_acc[wid] = acc; s_tac[wid] = tac; }
    __syncthreads();
    if (wid == 0) {
        acc = (lane < THREADS/32) ? s_acc[lane] : 0.0f;
        tac = (lane < THREADS/32) ? s_tac[lane] : 0.0f;
        #pragma unroll
        for (int off = 16; off > 0; off >>= 1) {
            acc += __shfl_xor_sync(0xffffffff, acc, off);
            tac += __shfl_xor_sync(0xffffffff, tac, off);
        }
        if (lane == 0) {
            atomicAdd(&g_overlap[bn], acc);
            if (n == 0) atomicAdd(&g_tarea[b], tac);
        }
    }
}

// grid: B*N blocks, one per box. Sums target_mask[b] over the box region
// (all integer-valued floats; exact), computes IoU, writes both outputs.
__global__ __launch_bounds__(THREADS)
void finalize_kernel(const float* __restrict__ target,
                     const int* __restrict__ boxes,
                     float* __restrict__ out) {
    const int bn = blockIdx.x;
    const int b  = bn >> 4;

    const int x1 = boxes[bn*4 + 0];
    const int y1 = boxes[bn*4 + 1];
    const int x2 = boxes[bn*4 + 2];
    const int y2 = boxes[bn*4 + 3];
    const int wbox = x2 - x1;
    const int hbox = y2 - y1;

    const float* tb = target + (size_t)b * HW;

    // one row per thread (strided); scalar inner loop over cols (L2-hot)
    float inter = 0.0f;
    for (int r = threadIdx.x; r < hbox; r += THREADS) {
        const float* row = tb + (size_t)(y1 + r) * WW + x1;
        float s = 0.0f;
        for (int c = 0; c < wbox; c++) s += row[c];
        inter += s;
    }

    __shared__ float s_red[THREADS/32];
    const int lane = threadIdx.x & 31;
    const int wid  = threadIdx.x >> 5;
    #pragma unroll
    for (int off = 16; off > 0; off >>= 1)
        inter += __shfl_xor_sync(0xffffffff, inter, off);
    if (lane == 0) s_red[wid] = inter;
    __syncthreads();
    if (threadIdx.x == 0) {
        float tot = 0.0f;
        #pragma unroll
        for (int w = 0; w < THREADS/32; w++) tot += s_red[w];
        const float box_area = (float)wbox * (float)hbox;
        const float uni = box_area + g_tarea[b] - tot;
        out[bn*2 + 0] = g_overlap[bn];
        out[bn*2 + 1] = tot / (uni + 1e-8f);
    }
}

extern "C" void kernel_launch(void* const* d_in, const int* in_sizes, int n_in,
                              void* d_out, int out_size) {
    const float* masks  = (const float*)d_in[0];
    const float* target = (const float*)d_in[1];
    const int*   boxes  = (const int*)d_in[2];
    float* out = (float*)d_out;

    zero_kernel<<<1, THREADS>>>();
    dim3 grid(CHUNKS, BB*NN);
    overlap_kernel<<<grid, THREADS>>>((const float4*)masks, (const float4*)target);
    finalize_kernel<<<BB*NN, THREADS>>>(target, boxes, out);
}

// round 2
// speedup vs baseline: 1.0212x; 1.0212x over previous
#include <cuda_runtime.h>
#include <cstdint>

#define BB 16
#define NN 16
#define HH 512
#define WW 512
#define HW (HH*WW)            // 262144 floats per plane
#define Q4 (HW/4)             // 65536 float4 per plane
#define TILE_F4 2048          // float4 per tile -> 32 KB smem
#define NCHUNK (Q4/TILE_F4)   // 32 chunks per plane
#define THREADS 256
#define ITERS (TILE_F4/THREADS)  // 8

// Deterministic per-chunk partials; every slot is written on every launch,
// so no zero-init and no atomics are needed.
__device__ float g_part_ov[BB*NN*NCHUNK];
__device__ float g_part_ta[BB*NCHUNK];

__device__ __forceinline__ float warp_sum(float v) {
    #pragma unroll
    for (int off = 16; off > 0; off >>= 1)
        v += __shfl_xor_sync(0xffffffff, v, off);
    return v;
}

// grid: (NCHUNK, BB). Stage one target tile in smem, stream all 16 mask
// planes against it. Target is read from DRAM exactly once.
__global__ __launch_bounds__(THREADS)
void overlap_kernel(const float4* __restrict__ masks,
                    const float4* __restrict__ target) {
    __shared__ float4 s_t[TILE_F4];            // 32 KB
    __shared__ float  s_red[NN * (THREADS/32)];// 16 n x 8 warps
    __shared__ float  s_ta[THREADS/32];

    const int b     = blockIdx.y;
    const int chunk = blockIdx.x;
    const int tid   = threadIdx.x;
    const int lane  = tid & 31;
    const int wid   = tid >> 5;

    // --- load target tile into smem, and its sum (for target_area) ---
    const float4* t = target + (size_t)b * Q4 + (size_t)chunk * TILE_F4;
    float tac = 0.0f;
    #pragma unroll
    for (int k = 0; k < ITERS; k++) {
        const int i = tid + k * THREADS;
        float4 v = t[i];
        s_t[i] = v;
        tac += v.x + v.y + v.z + v.w;
    }
    tac = warp_sum(tac);
    if (lane == 0) s_ta[wid] = tac;
    __syncthreads();

    // --- stream the 16 mask planes of this batch against the smem tile ---
    const float4* mbase = masks + ((size_t)b * NN) * Q4 + (size_t)chunk * TILE_F4;
    #pragma unroll 1
    for (int n = 0; n < NN; n++) {
        const float4* m = mbase + (size_t)n * Q4;
        float acc = 0.0f;
        #pragma unroll
        for (int k = 0; k < ITERS; k++) {
            const int i = tid + k * THREADS;
            float4 a = m[i];
            float4 c = s_t[i];
            acc += a.x*c.x + a.y*c.y + a.z*c.z + a.w*c.w;
        }
        acc = warp_sum(acc);
        if (lane == 0) s_red[n * (THREADS/32) + wid] = acc;
    }
    __syncthreads();

    // --- write per-chunk partials (one thread per n; one for target area) ---
    if (tid < NN) {
        float s = 0.0f;
        #pragma unroll
        for (int w = 0; w < THREADS/32; w++) s += s_red[tid * (THREADS/32) + w];
        g_part_ov[((size_t)b * NN + tid) * NCHUNK + chunk] = s;
    }
    if (tid == NN) {
        float s = 0.0f;
        #pragma unroll
        for (int w = 0; w < THREADS/32; w++) s += s_ta[w];
        g_part_ta[b * NCHUNK + chunk] = s;
    }
}

// grid: B*N blocks, one per box. Sums target_mask[b] over the box region
// (values are integer-valued floats; exact), folds partials, writes output.
__global__ __launch_bounds__(THREADS)
void finalize_kernel(const float* __restrict__ target,
                     const int* __restrict__ boxes,
                     float* __restrict__ out) {
    const int bn = blockIdx.x;
    const int b  = bn >> 4;
    const int tid  = threadIdx.x;
    const int lane = tid & 31;
    const int wid  = tid >> 5;

    __shared__ float s_red[THREADS/32];
    __shared__ float s_ov, s_ta;

    // warp 0 folds the overlap partials; warp 1 folds target-area partials
    if (wid == 0) {
        float v = g_part_ov[(size_t)bn * NCHUNK + lane];
        v = warp_sum(v);
        if (lane == 0) s_ov = v;
    } else if (wid == 1) {
        float v = g_part_ta[b * NCHUNK + lane];
        v = warp_sum(v);
        if (lane == 0) s_ta = v;
    }

    const int x1 = boxes[bn*4 + 0];
    const int y1 = boxes[bn*4 + 1];
    const int x2 = boxes[bn*4 + 2];
    const int y2 = boxes[bn*4 + 3];
    const int wbox = x2 - x1;
    const int hbox = y2 - y1;

    const float* tb = target + (size_t)b * HW;

    // one row per thread (hbox <= 255 < THREADS); 4 accumulators to break
    // the dependent-add chain on the L2-hot row scan
    float inter = 0.0f;
    for (int r = tid; r < hbox; r += THREADS) {
        const float* row = tb + (size_t)(y1 + r) * WW + x1;
        float s0 = 0.f, s1 = 0.f, s2 = 0.f, s3 = 0.f;
        int c = 0;
        for (; c + 4 <= wbox; c += 4) {
            s0 += row[c+0]; s1 += row[c+1]; s2 += row[c+2]; s3 += row[c+3];
        }
        for (; c < wbox; c++) s0 += row[c];
        inter += (s0 + s1) + (s2 + s3);
    }
    inter = warp_sum(inter);
    if (lane == 0) s_red[wid] = inter;
    __syncthreads();

    if (tid == 0) {
        float tot = 0.0f;
        #pragma unroll
        for (int w = 0; w < THREADS/32; w++) tot += s_red[w];
        const float box_area = (float)wbox * (float)hbox;
        const float uni = box_area + s_ta - tot;
        out[bn*2 + 0] = s_ov;
        out[bn*2 + 1] = tot / (uni + 1e-8f);
    }
}

extern "C" void kernel_launch(void* const* d_in, const int* in_sizes, int n_in,
                              void* d_out, int out_size) {
    const float* masks  = (const float*)d_in[0];
    const float* target = (const float*)d_in[1];
    const int*   boxes  = (const int*)d_in[2];
    float* out = (float*)d_out;

    dim3 grid(NCHUNK, BB);
    overlap_kernel<<<grid, THREADS>>>((const float4*)masks, (const float4*)target);
    finalize_kernel<<<BB*NN, THREADS>>>(target, boxes, out);
}

// round 3
// speedup vs baseline: 1.4674x; 1.4370x over previous
#include <cuda_runtime.h>
#include <cstdint>

#define BB 16
#define NN 16
#define HH 512
#define WW 512
#define HW (HH*WW)            // 262144 floats per plane
#define Q4 (HW/4)             // 65536 float4 per plane
#define TILE_F4 2048          // float4 per tile -> 32 KB smem = 16 full rows
#define TILE_ROWS 16
#define NCHUNK (Q4/TILE_F4)   // 32 chunks per plane
#define THREADS 256
#define ITERS (TILE_F4/THREADS)  // 8

// Deterministic per-chunk partials; every slot written on every launch,
// so no zero-init and no atomics are needed. NCHUNK == 32 == warp size.
__device__ float g_part_ov[BB*NN*NCHUNK];   // overlap partials
__device__ float g_part_in[BB*NN*NCHUNK];   // box-intersection partials
__device__ float g_part_ta[BB*NCHUNK];      // target-area partials

__device__ __forceinline__ float warp_sum(float v) {
    #pragma unroll
    for (int off = 16; off > 0; off >>= 1)
        v += __shfl_xor_sync(0xffffffff, v, off);
    return v;
}

// grid: (NCHUNK, BB). Stage one 16-row target tile in smem, stream all 16
// mask planes against it (DRAM-bound part), then compute per-box
// intersection partials from the smem tile (hidden under memory stalls).
__global__ __launch_bounds__(THREADS)
void overlap_kernel(const float4* __restrict__ masks,
                    const float4* __restrict__ target,
                    const int4*   __restrict__ boxes) {
    __shared__ float4 s_t[TILE_F4];            // 32 KB: rows are 128 float4 each
    __shared__ float  s_red[NN * (THREADS/32)];
    __shared__ float  s_ta[THREADS/32];

    const int b     = blockIdx.y;
    const int chunk = blockIdx.x;
    const int tid   = threadIdx.x;
    const int lane  = tid & 31;
    const int wid   = tid >> 5;

    // --- load target tile into smem + accumulate its sum (target_area) ---
    const float4* t = target + (size_t)b * Q4 + (size_t)chunk * TILE_F4;
    float tac = 0.0f;
    #pragma unroll
    for (int k = 0; k < ITERS; k++) {
        const int i = tid + k * THREADS;
        float4 v = t[i];
        s_t[i] = v;
        tac += v.x + v.y + v.z + v.w;
    }
    tac = warp_sum(tac);
    if (lane == 0) s_ta[wid] = tac;
    __syncthreads();

    // --- stream the 16 mask planes of this batch against the smem tile ---
    const float4* mbase = masks + ((size_t)b * NN) * Q4 + (size_t)chunk * TILE_F4;
    #pragma unroll 1
    for (int n = 0; n < NN; n++) {
        const float4* m = mbase + (size_t)n * Q4;
        float acc = 0.0f;
        #pragma unroll
        for (int k = 0; k < ITERS; k++) {
            const int i = tid + k * THREADS;
            float4 a = m[i];
            float4 c = s_t[i];
            acc += a.x*c.x + a.y*c.y + a.z*c.z + a.w*c.w;
        }
        acc = warp_sum(acc);
        if (lane == 0) s_red[n * (THREADS/32) + wid] = acc;
    }

    // --- box-intersection partials from the smem tile (conflict-free:
    //     lanes scan consecutive columns). Warp w handles boxes w and w+8. ---
    {
        const float* tf  = (const float*)s_t;      // 16 rows x 512 floats
        const int row0   = chunk * TILE_ROWS;      // first global row of tile
        #pragma unroll
        for (int pass = 0; pass < 2; pass++) {
            const int nb = wid + pass * 8;
            const int4 bx = boxes[b * NN + nb];    // x1,y1,x2,y2
            const int rlo = max(bx.y - row0, 0);
            const int rhi = min(bx.w - row0, TILE_ROWS);
            float acc = 0.0f;
            for (int r = rlo; r < rhi; r++) {
                const float* row = tf + r * WW;
                for (int c = bx.x + lane; c < bx.z; c += 32)
                    acc += row[c];
            }
            acc = warp_sum(acc);
            if (lane == 0)
                g_part_in[((size_t)b * NN + nb) * NCHUNK + chunk] = acc;
        }
    }
    __syncthreads();

    // --- write remaining per-chunk partials ---
    if (tid < NN) {
        float s = 0.0f;
        #pragma unroll
        for (int w = 0; w < THREADS/32; w++) s += s_red[tid * (THREADS/32) + w];
        g_part_ov[((size_t)b * NN + tid) * NCHUNK + chunk] = s;
    }
    if (tid == NN) {
        float s = 0.0f;
        #pragma unroll
        for (int w = 0; w < THREADS/32; w++) s += s_ta[w];
        g_part_ta[b * NCHUNK + chunk] = s;
    }
}

// grid: B*N blocks of ONE warp. Fold the 32 chunk partials (lane == chunk)
// for overlap / intersection / target-area, compute IoU, write output.
__global__ __launch_bounds__(32)
void finalize_kernel(const int4* __restrict__ boxes,
                     float* __restrict__ out) {
    const int bn   = blockIdx.x;
    const int b    = bn >> 4;
    const int lane = threadIdx.x;

    float ov = g_part_ov[(size_t)bn * NCHUNK + lane];
    float in = g_part_in[(size_t)bn * NCHUNK + lane];
    float ta = g_part_ta[b * NCHUNK + lane];
    ov = warp_sum(ov);
    in = warp_sum(in);
    ta = warp_sum(ta);

    if (lane == 0) {
        const int4 bx = boxes[bn];
        const float box_area = (float)(bx.z - bx.x) * (float)(bx.w - bx.y);
        const float uni = box_area + ta - in;
        out[bn*2 + 0] = ov;
        out[bn*2 + 1] = in / (uni + 1e-8f);
    }
}

extern "C" void kernel_launch(void* const* d_in, const int* in_sizes, int n_in,
                              void* d_out, int out_size) {
    const float* masks  = (const float*)d_in[0];
    const float* target = (const float*)d_in[1];
    const int4*  boxes  = (const int4*)d_in[2];
    float* out = (float*)d_out;

    dim3 grid(NCHUNK, BB);
    overlap_kernel<<<grid, THREADS>>>((const float4*)masks,
                                      (const float4*)target, boxes);
    finalize_kernel<<<BB*NN, 32>>>(boxes, out);
}

// round 6
// speedup vs baseline: 1.6528x; 1.1264x over previous
#include <cuda_runtime.h>
#include <cstdint>

#define BB 16
#define NN 16
#define HH 512
#define WW 512
#define HW (HH*WW)            // 262144 floats per plane
#define Q4 (HW/4)             // 65536 float4 per plane
#define TILE_F4 1024          // float4 per tile -> 16 KB smem = 8 full rows
#define TILE_ROWS 8
#define NCHUNK (Q4/TILE_F4)   // 64 chunks per plane
#define THREADS 256
#define ITERS (TILE_F4/THREADS)  // 4

// Deterministic per-chunk partials; every slot written on every launch,
// so no zero-init and no atomics are needed.
__device__ float g_part_ov[BB*NN*NCHUNK];   // overlap partials
__device__ float g_part_in[BB*NN*NCHUNK];   // box-intersection partials
__device__ float g_part_ta[BB*NCHUNK];      // target-area partials

__device__ __forceinline__ float warp_sum(float v) {
    #pragma unroll
    for (int off = 16; off > 0; off >>= 1)
        v += __shfl_xor_sync(0xffffffff, v, off);
    return v;
}

// grid: (NCHUNK, BB). Stage one 8-row target tile in smem, stream all 16
// mask planes against it (DRAM-bound), then compute per-box intersection
// partials from the smem tile with LDS.128 (hidden under memory stalls).
__global__ __launch_bounds__(THREADS)
void overlap_kernel(const float4* __restrict__ masks,
                    const float4* __restrict__ target,
                    const int4*   __restrict__ boxes) {
    __shared__ float4 s_t[TILE_F4];            // 16 KB: 8 rows x 128 float4
    __shared__ float  s_red[NN * (THREADS/32)];
    __shared__ float  s_ta[THREADS/32];

    const int b     = blockIdx.y;
    const int chunk = blockIdx.x;
    const int tid   = threadIdx.x;
    const int lane  = tid & 31;
    const int wid   = tid >> 5;

    // --- load target tile into smem + accumulate its sum (target_area) ---
    const float4* t = target + (size_t)b * Q4 + (size_t)chunk * TILE_F4;
    float tac = 0.0f;
    #pragma unroll
    for (int k = 0; k < ITERS; k++) {
        const int i = tid + k * THREADS;
        float4 v = t[i];
        s_t[i] = v;
        tac += v.x + v.y + v.z + v.w;
    }
    tac = warp_sum(tac);
    if (lane == 0) s_ta[wid] = tac;
    __syncthreads();

    // --- stream the 16 mask planes against the smem tile.
    //     Fully unrolled so acc[] stays in registers; all 16 warp
    //     reductions are deferred (independent shuffle chains pipeline). ---
    const float4* mbase = masks + ((size_t)b * NN) * Q4 + (size_t)chunk * TILE_F4;
    float acc[NN];
    #pragma unroll
    for (int n = 0; n < NN; n++) {
        const float4* m = mbase + (size_t)n * Q4;
        float a0 = 0.0f;
        #pragma unroll
        for (int k = 0; k < ITERS; k++) {
            const int i = tid + k * THREADS;
            float4 a = m[i];
            float4 c = s_t[i];
            a0 += a.x*c.x + a.y*c.y + a.z*c.z + a.w*c.w;
        }
        acc[n] = a0;
    }
    #pragma unroll
    for (int n = 0; n < NN; n++) {
        acc[n] = warp_sum(acc[n]);
        if (lane == 0) s_red[n * (THREADS/32) + wid] = acc[n];
    }

    // --- box-intersection partials from the smem tile, LDS.128 middle +
    //     scalar head/tail. Warp w handles boxes w and w+8. ---
    {
        const float* tf = (const float*)s_t;       // 8 rows x 512 floats
        const int row0  = chunk * TILE_ROWS;
        #pragma unroll
        for (int pass = 0; pass < 2; pass++) {
            const int nb = wid + pass * 8;
            const int4 bx = boxes[b * NN + nb];    // x1,y1,x2,y2
            const int rlo = max(bx.y - row0, 0);
            const int rhi = min(bx.w - row0, TILE_ROWS);
            const int a0 = (bx.x + 3) & ~3;        // first 16B-aligned col
            const int a1 = bx.z & ~3;              // end of aligned region
            float s = 0.0f;
            if (a1 <= a0) {                        // narrow box: pure scalar
                for (int r = rlo; r < rhi; r++) {
                    const float* row = tf + r * WW;
                    for (int c = bx.x + lane; c < bx.z; c += 32)
                        s += row[c];
                }
            } else {
                const int n4 = (a1 - a0) >> 2;
                for (int r = rlo; r < rhi; r++) {
                    const float* row = tf + r * WW;
                    if (lane < a0 - bx.x) s += row[bx.x + lane];   // head <=3
                    if (lane < bx.z - a1) s += row[a1 + lane];     // tail <=3
                    const float4* r4 = (const float4*)(row + a0);
                    for (int i = lane; i < n4; i += 32) {
                        float4 v = r4[i];
                        s += (v.x + v.y) + (v.z + v.w);
                    }
                }
            }
            s = warp_sum(s);
            if (lane == 0)
                g_part_in[((size_t)b * NN + nb) * NCHUNK + chunk] = s;
        }
    }
    __syncthreads();

    // --- write remaining per-chunk partials ---
    if (tid < NN) {
        float s = 0.0f;
        #pragma unroll
        for (int w = 0; w < THREADS/32; w++) s += s_red[tid * (THREADS/32) + w];
        g_part_ov[((size_t)b * NN + tid) * NCHUNK + chunk] = s;
    }
    if (tid == NN) {
        float s = 0.0f;
        #pragma unroll
        for (int w = 0; w < THREADS/32; w++) s += s_ta[w];
        g_part_ta[b * NCHUNK + chunk] = s;
    }
}

// grid: 32 blocks x 8 warps; warp w of block g handles bn = g*8 + w.
// Each lane folds chunks (lane) and (lane+32).
__global__ __launch_bounds__(THREADS)
void finalize_kernel(const int4* __restrict__ boxes,
                     float* __restrict__ out) {
    const int wid  = threadIdx.x >> 5;
    const int lane = threadIdx.x & 31;
    const int bn   = blockIdx.x * 8 + wid;
    const int b    = bn >> 4;

    float ov = g_part_ov[(size_t)bn * NCHUNK + lane]
             + g_part_ov[(size_t)bn * NCHUNK + lane + 32];
    float in = g_part_in[(size_t)bn * NCHUNK + lane]
             + g_part_in[(size_t)bn * NCHUNK + lane + 32];
    float ta = g_part_ta[b * NCHUNK + lane]
             + g_part_ta[b * NCHUNK + lane + 32];
    ov = warp_sum(ov);
    in = warp_sum(in);
    ta = warp_sum(ta);

    if (lane == 0) {
        const int4 bx = boxes[bn];
        const float box_area = (float)(bx.z - bx.x) * (float)(bx.w - bx.y);
        const float uni = box_area + ta - in;
        out[bn*2 + 0] = ov;
        out[bn*2 + 1] = in / (uni + 1e-8f);
    }
}

extern "C" void kernel_launch(void* const* d_in, const int* in_sizes, int n_in,
                              void* d_out, int out_size) {
    const float* masks  = (const float*)d_in[0];
    const float* target = (const float*)d_in[1];
    const int4*  boxes  = (const int4*)d_in[2];
    float* out = (float*)d_out;

    dim3 grid(NCHUNK, BB);
    overlap_kernel<<<grid, THREADS>>>((const float4*)masks,
                                      (const float4*)target, boxes);
    finalize_kernel<<<32, THREADS>>>(boxes, out);
}